// round 2
// baseline (speedup 1.0000x reference)
#include <cuda_runtime.h>

#define BB 4
#define CK 64
#define NKEY 8192
#define MQ 1024
#define CVAL 512
#define BM 32
#define BN 32
#define NTHREADS 256

// Shared memory layout (float offsets)
#define SOFF_QS   0          // 64*32
#define SOFF_KS   2048       // 64*32
#define SOFF_PS   4096       // 32 rows * 36 (padded)
#define SOFF_ASQ  5248       // 32
#define SOFF_QSQ  5280       // 32
#define SOFF_RED  5312       // 256
#define SOFF_SUM  5568       // 32
#define SOFF_VS   5600       // 512 rows * 36 (padded)
#define SMEM_FLOATS (5600 + 512*36)
#define SMEM_BYTES  (SMEM_FLOATS * 4)

__device__ float g_asq[BB * NKEY];

// Precompute |a_n|^2 for all memory tokens. Coalesced over n.
__global__ void asq_kernel(const float* __restrict__ mk) {
    int i = blockIdx.x * blockDim.x + threadIdx.x;
    if (i >= BB * NKEY) return;
    int b = i >> 13;              // NKEY = 8192
    int n = i & (NKEY - 1);
    const float* p = mk + ((size_t)b * CK) * NKEY + n;
    float s = 0.f;
#pragma unroll 8
    for (int c = 0; c < CK; ++c) { float v = p[(size_t)c * NKEY]; s = fmaf(v, v, s); }
    g_asq[i] = s;
}

#define FMA2(d, a, bb) asm("fma.rn.f32x2 %0, %1, %2, %0;" : "+l"(d) : "l"(a), "l"(bb))
#define PACK2(d, lo, hi) asm("mov.b64 %0, {%1, %2};" : "=l"(d) : "r"(__float_as_uint(lo)), "r"(__float_as_uint(hi)))

__global__ void __launch_bounds__(NTHREADS, 1)
mr_main_kernel(const float* __restrict__ mk, const float* __restrict__ qk,
               const float* __restrict__ mv, float* __restrict__ out)
{
    extern __shared__ float sm[];
    float* S_QS  = sm + SOFF_QS;
    float* S_KS  = sm + SOFF_KS;
    float* S_PS  = sm + SOFF_PS;
    float* S_ASQ = sm + SOFF_ASQ;
    float* S_QSQ = sm + SOFF_QSQ;
    float* S_RED = sm + SOFF_RED;
    float* S_SUM = sm + SOFF_SUM;
    float* S_VS  = sm + SOFF_VS;

    const int tid = threadIdx.x;
    const int b   = blockIdx.y;
    const int m0  = blockIdx.x * BM;

    // ---- load Q block: qs[c][m], 512 float4 ----
#pragma unroll
    for (int k = 0; k < 2; ++k) {
        int i = tid + k * NTHREADS;
        int c = i >> 3, g = (i & 7) * 4;
        float4 v = *(const float4*)(qk + ((size_t)(b * CK + c)) * MQ + m0 + g);
        *(float4*)(S_QS + c * 32 + g) = v;
    }
    __syncthreads();
    if (tid < 32) {
        float s = 0.f;
#pragma unroll 8
        for (int c = 0; c < CK; ++c) { float q = S_QS[c * 32 + tid]; s = fmaf(q, q, s); }
        S_QSQ[tid] = s;
    }

    // thread roles
    const int nnb   = (tid & 7) * 4;   // logit phase: 4 keys
    const int lm    = tid >> 3;        //              1 query
    const int sm_m  = tid & 31;        // sumexp partial
    const int sm_n  = (tid >> 5) * 4;
    const int mgrp  = tid & 3;         // accumulate: 8 m
    const int cgrp  = tid >> 2;        //             8 c (interleaved stride 64)
    const int m_base = mgrp * 8;

    unsigned long long acc[8][4];
#pragma unroll
    for (int i = 0; i < 8; ++i)
#pragma unroll
        for (int j = 0; j < 4; ++j) acc[i][j] = 0ull;
    float se = 0.f;

    const float* mk_b = mk + ((size_t)b * CK) * NKEY;
    const float* mv_b = mv + ((size_t)b * CVAL) * NKEY;

    for (int n0 = 0; n0 < NKEY; n0 += BN) {
        __syncthreads();
        // ---- stage mk chunk ks[c][nn] ----
#pragma unroll
        for (int k = 0; k < 2; ++k) {
            int i = tid + k * NTHREADS;
            int c = i >> 3, g = (i & 7) * 4;
            float4 v = *(const float4*)(mk_b + (size_t)c * NKEY + n0 + g);
            *(float4*)(S_KS + c * 32 + g) = v;
        }
        // ---- stage mv chunk vs[c][nn], padded rows of 36 ----
#pragma unroll
        for (int k = 0; k < 16; ++k) {
            int i = tid + k * NTHREADS;
            int c = i >> 3, g = (i & 7) * 4;
            float4 v = *(const float4*)(mv_b + (size_t)c * NKEY + n0 + g);
            *(float4*)(S_VS + c * 36 + g) = v;
        }
        if (tid < 32) S_ASQ[tid] = g_asq[b * NKEY + n0 + tid];
        __syncthreads();

        // ---- logits + exp: thread computes 4 (nn) x 1 (m) ----
        {
            float d0 = 0.f, d1 = 0.f, d2 = 0.f, d3 = 0.f;
#pragma unroll 16
            for (int c = 0; c < CK; ++c) {
                float4 k4 = *(const float4*)(S_KS + c * 32 + nnb);
                float q = S_QS[c * 32 + lm];
                d0 = fmaf(k4.x, q, d0);
                d1 = fmaf(k4.y, q, d1);
                d2 = fmaf(k4.z, q, d2);
                d3 = fmaf(k4.w, q, d3);
            }
            float qq = S_QSQ[lm];
            S_PS[(nnb + 0) * 36 + lm] = __expf((2.f * d0 - S_ASQ[nnb + 0] - qq) * 0.125f);
            S_PS[(nnb + 1) * 36 + lm] = __expf((2.f * d1 - S_ASQ[nnb + 1] - qq) * 0.125f);
            S_PS[(nnb + 2) * 36 + lm] = __expf((2.f * d2 - S_ASQ[nnb + 2] - qq) * 0.125f);
            S_PS[(nnb + 3) * 36 + lm] = __expf((2.f * d3 - S_ASQ[nnb + 3] - qq) * 0.125f);
        }
        __syncthreads();

        // ---- sumexp partials (distributed, fixed slots) ----
        se += S_PS[(sm_n + 0) * 36 + sm_m] + S_PS[(sm_n + 1) * 36 + sm_m]
            + S_PS[(sm_n + 2) * 36 + sm_m] + S_PS[(sm_n + 3) * 36 + sm_m];

        // ---- accumulate: acc[c][m] += v[c][nn] * p[nn][m], f32x2 over m-pairs ----
#pragma unroll 1
        for (int blk = 0; blk < 8; ++blk) {
            const int nn0 = blk * 4;
            unsigned long long p2[4][4];
#pragma unroll
            for (int j = 0; j < 4; ++j) {
                const float* pp = S_PS + (nn0 + j) * 36 + m_base;
                ulonglong2 t0 = *(const ulonglong2*)(pp);
                ulonglong2 t1 = *(const ulonglong2*)(pp + 4);
                p2[j][0] = t0.x; p2[j][1] = t0.y; p2[j][2] = t1.x; p2[j][3] = t1.y;
            }
#pragma unroll
            for (int ci = 0; ci < 8; ++ci) {
                const float4 v = *(const float4*)(S_VS + (cgrp + ci * 64) * 36 + nn0);
                unsigned long long vv;
                PACK2(vv, v.x, v.x);
                FMA2(acc[ci][0], vv, p2[0][0]); FMA2(acc[ci][1], vv, p2[0][1]);
                FMA2(acc[ci][2], vv, p2[0][2]); FMA2(acc[ci][3], vv, p2[0][3]);
                PACK2(vv, v.y, v.y);
                FMA2(acc[ci][0], vv, p2[1][0]); FMA2(acc[ci][1], vv, p2[1][1]);
                FMA2(acc[ci][2], vv, p2[1][2]); FMA2(acc[ci][3], vv, p2[1][3]);
                PACK2(vv, v.z, v.z);
                FMA2(acc[ci][0], vv, p2[2][0]); FMA2(acc[ci][1], vv, p2[2][1]);
                FMA2(acc[ci][2], vv, p2[2][2]); FMA2(acc[ci][3], vv, p2[2][3]);
                PACK2(vv, v.w, v.w);
                FMA2(acc[ci][0], vv, p2[3][0]); FMA2(acc[ci][1], vv, p2[3][1]);
                FMA2(acc[ci][2], vv, p2[3][2]); FMA2(acc[ci][3], vv, p2[3][3]);
            }
        }
    }

    // ---- reduce sumexp across the 8 nn-slot groups ----
    __syncthreads();
    S_RED[(tid >> 5) * 32 + (tid & 31)] = se;
    __syncthreads();
    if (tid < 32) {
        float s = 0.f;
#pragma unroll
        for (int g = 0; g < 8; ++g) s += S_RED[g * 32 + tid];
        S_SUM[tid] = 1.0f / s;
    }
    __syncthreads();

    float r[8];
#pragma unroll
    for (int k = 0; k < 8; ++k) r[k] = S_SUM[m_base + k];

#pragma unroll
    for (int ci = 0; ci < 8; ++ci) {
        int c = cgrp + ci * 64;
        float* po = out + ((size_t)(b * CVAL + c)) * MQ + m0 + m_base;
#pragma unroll
        for (int mp = 0; mp < 4; ++mp) {
            unsigned int u0, u1;
            asm("mov.b64 {%0, %1}, %2;" : "=r"(u0), "=r"(u1) : "l"(acc[ci][mp]));
            float2 o;
            o.x = __uint_as_float(u0) * r[2 * mp + 0];
            o.y = __uint_as_float(u1) * r[2 * mp + 1];
            *(float2*)(po + 2 * mp) = o;
        }
    }
}

extern "C" void kernel_launch(void* const* d_in, const int* in_sizes, int n_in,
                              void* d_out, int out_size) {
    const float* mk = (const float*)d_in[0];
    const float* qk = (const float*)d_in[1];
    const float* mv = (const float*)d_in[2];
    float* out = (float*)d_out;

    asq_kernel<<<(BB * NKEY + 255) / 256, 256>>>(mk);

    cudaFuncSetAttribute(mr_main_kernel,
                         cudaFuncAttributeMaxDynamicSharedMemorySize, SMEM_BYTES);
    dim3 grid(MQ / BM, BB);
    mr_main_kernel<<<grid, NTHREADS, SMEM_BYTES>>>(mk, qk, mv, out);
}